// round 1
// baseline (speedup 1.0000x reference)
#include <cuda_runtime.h>
#include <math.h>

// Problem constants
#define NN 4096
#define KK 64
#define AA 8
#define DD 128
#define NU_ 100000
#define NR_ 32
#define NA_ 5000

// Scratch (device globals: allocation-free per harness rules)
__device__ float g_Tu[(size_t)NU_ * 256];   // u2e @ W1[256:384]   (102.4 MB)
__device__ float g_Ta[(size_t)NA_ * 256];   // ua2e @ W1[384:512]  (5.12 MB)
__device__ float g_Tr1[NR_ * 256];          // r2e @ W1[0:128]
__device__ float g_Tr2[NR_ * 256];          // r2e @ W1[128:256]
__device__ float g_se[NN * DD];             // u2e[nodes] @ A1[128:256] + ab1

// -------------------------------------------------------------------------
// Precompute: out[r][j] = sum_i emb[r][i] * Wb[i*256 + j],  j in [0,256)
// One block = 16 rows, 256 threads (1 output col each).
// -------------------------------------------------------------------------
__global__ __launch_bounds__(256) void table_kernel(
    const float* __restrict__ emb, const float* __restrict__ Wb,
    int rows, int which)
{
    float* out = (which == 0) ? g_Tu : (which == 1) ? g_Ta
               : (which == 2) ? g_Tr1 : g_Tr2;

    __shared__ float s_e[16][128];
    const int r0 = blockIdx.x * 16;
    const int tid = threadIdx.x;

    for (int i = tid; i < 16 * 128; i += 256) {
        int r = i >> 7, c = i & 127;
        int rr = r0 + r;
        s_e[r][c] = (rr < rows) ? emb[(size_t)rr * 128 + c] : 0.f;
    }
    __syncthreads();

    float acc[16];
    #pragma unroll
    for (int r = 0; r < 16; r++) acc[r] = 0.f;

    const int j = tid;
    #pragma unroll 2
    for (int i = 0; i < 128; i++) {
        float w = Wb[i * 256 + j];
        #pragma unroll
        for (int r = 0; r < 16; r++)
            acc[r] = fmaf(s_e[r][i], w, acc[r]);
    }
    #pragma unroll
    for (int r = 0; r < 16; r++) {
        int rr = r0 + r;
        if (rr < rows) out[(size_t)rr * 256 + j] = acc[r];
    }
}

// -------------------------------------------------------------------------
// Precompute per-node self-embedding attention term:
//   g_se[n][d] = ab1[d] + sum_i u2e[nodes[n]][i] * A1[(128+i)*128 + d]
// -------------------------------------------------------------------------
__global__ __launch_bounds__(128) void se_kernel(
    const int* __restrict__ nodes, const float* __restrict__ u2e,
    const float* __restrict__ A1, const float* __restrict__ ab1)
{
    const int n = blockIdx.x;
    const int d = threadIdx.x;
    __shared__ float s[128];
    s[d] = u2e[(size_t)nodes[n] * 128 + d];
    __syncthreads();
    float acc = ab1[d];
    #pragma unroll 4
    for (int i = 0; i < 128; i++)
        acc = fmaf(s[i], A1[(128 + i) * 128 + d], acc);
    g_se[n * 128 + d] = acc;
}

// -------------------------------------------------------------------------
// Main fused kernel: one block per node (grid 4096), 256 threads.
// smem: s_h1[64*256] | s_h[64*128] | misc. 102400 bytes total.
// -------------------------------------------------------------------------
__global__ __launch_bounds__(256, 2) void agg_kernel(
    const int* __restrict__ prel, const int* __restrict__ pnbr,
    const int* __restrict__ attrs,
    const float* __restrict__ b1, const float* __restrict__ W2,
    const float* __restrict__ b2, const float* __restrict__ A1,
    const float* __restrict__ A2, const float* __restrict__ A3,
    const float* __restrict__ ab2, const float* __restrict__ ab3,
    float* __restrict__ out)
{
    extern __shared__ float sm[];
    float* s_h1 = sm;                 // 16384 floats (h1, later a1 / a2)
    float* s_h  = sm + 16384;         // 8192 floats
    float* s_se = sm + 24576;         // 128
    float* s_A3 = sm + 24704;         // 128
    float* s_lg = sm + 24832;         // 64
    int*   s_rel  = (int*)(sm + 24896);   // 128 ints
    int*   s_nbr  = s_rel + 128;          // 64
    int*   s_attr = s_nbr + 64;           // 512   -> ends at float-index 25600

    float* s_a  = s_h1;               // a1 overlays h1[0:8192]
    float* s_a2 = s_h1 + 8192;        // a2 overlays h1[8192:16384]

    const int n = blockIdx.x;
    const int t = threadIdx.x;

    if (t < 128) s_rel[t] = prel[n * 128 + t];
    if (t < 64)  s_nbr[t] = pnbr[n * 64 + t];
    for (int i = t; i < 512; i += 256) s_attr[i] = attrs[n * 512 + i];
    if (t < 128) { s_se[t] = g_se[n * 128 + t]; s_A3[t] = A3[t]; }
    __syncthreads();

    // ---- Step 1: h1[k][:] = relu(b1 + Tr1[r0] + Tr2[r1] + Tu[nbr] + sum_a Ta[attr]) ----
    {
        const int ksub = t >> 6;      // 4 paths processed concurrently
        const int jj = t & 63;        // float4 column group (256 cols / 4)
        const float4* b1v = (const float4*)b1;
        for (int kb = 0; kb < 16; kb++) {
            const int k = kb * 4 + ksub;
            const int r0 = s_rel[2 * k], r1 = s_rel[2 * k + 1], nb = s_nbr[k];
            float4 acc = b1v[jj];
            float4 v;
            v = ((const float4*)(g_Tr1 + r0 * 256))[jj];
            acc.x += v.x; acc.y += v.y; acc.z += v.z; acc.w += v.w;
            v = ((const float4*)(g_Tr2 + r1 * 256))[jj];
            acc.x += v.x; acc.y += v.y; acc.z += v.z; acc.w += v.w;
            v = ((const float4*)(g_Tu + (size_t)nb * 256))[jj];
            acc.x += v.x; acc.y += v.y; acc.z += v.z; acc.w += v.w;
            #pragma unroll
            for (int a = 0; a < 8; a++) {
                v = ((const float4*)(g_Ta + (size_t)s_attr[k * 8 + a] * 256))[jj];
                acc.x += v.x; acc.y += v.y; acc.z += v.z; acc.w += v.w;
            }
            acc.x = fmaxf(acc.x, 0.f); acc.y = fmaxf(acc.y, 0.f);
            acc.z = fmaxf(acc.z, 0.f); acc.w = fmaxf(acc.w, 0.f);
            ((float4*)(s_h1 + k * 256))[jj] = acc;
        }
    }
    __syncthreads();

    // ---- Step 2: h[k][d] = relu(b2[d] + sum_j h1[k][j] * W2[j][d]) ----
    {
        const int d0 = (t & 63) * 2;
        const int kg = t >> 6;                      // 16-path chunk
        float2 acc[16];
        const float bx = b2[d0], by = b2[d0 + 1];
        #pragma unroll
        for (int r = 0; r < 16; r++) { acc[r].x = bx; acc[r].y = by; }
        const float* hb = s_h1 + kg * 16 * 256;
        #pragma unroll 2
        for (int j = 0; j < 256; j++) {
            const float2 w = *(const float2*)(W2 + j * 128 + d0);
            #pragma unroll
            for (int r = 0; r < 16; r++) {
                const float hv = hb[r * 256 + j];
                acc[r].x = fmaf(hv, w.x, acc[r].x);
                acc[r].y = fmaf(hv, w.y, acc[r].y);
            }
        }
        #pragma unroll
        for (int r = 0; r < 16; r++) {
            float2 o; o.x = fmaxf(acc[r].x, 0.f); o.y = fmaxf(acc[r].y, 0.f);
            *(float2*)(s_h + (kg * 16 + r) * 128 + d0) = o;
        }
    }
    __syncthreads();

    // ---- Step 3: a1[k][d] = relu(se[d] + sum_j h[k][j] * A1[j][d]) ----
    {
        const int d0 = (t & 63) * 2;
        const int kg = t >> 6;
        float2 acc[16];
        const float sx = s_se[d0], sy = s_se[d0 + 1];
        #pragma unroll
        for (int r = 0; r < 16; r++) { acc[r].x = sx; acc[r].y = sy; }
        const float* hb = s_h + kg * 16 * 128;
        #pragma unroll 2
        for (int j = 0; j < 128; j++) {
            const float2 w = *(const float2*)(A1 + j * 128 + d0);
            #pragma unroll
            for (int r = 0; r < 16; r++) {
                const float hv = hb[r * 128 + j];
                acc[r].x = fmaf(hv, w.x, acc[r].x);
                acc[r].y = fmaf(hv, w.y, acc[r].y);
            }
        }
        #pragma unroll
        for (int r = 0; r < 16; r++) {
            float2 o; o.x = fmaxf(acc[r].x, 0.f); o.y = fmaxf(acc[r].y, 0.f);
            *(float2*)(s_a + (kg * 16 + r) * 128 + d0) = o;
        }
    }
    __syncthreads();

    // ---- Step 4: a2[k][d] = relu(ab2[d] + sum_j a1[k][j] * A2[j][d]) ----
    {
        const int d0 = (t & 63) * 2;
        const int kg = t >> 6;
        float2 acc[16];
        const float bx = ab2[d0], by = ab2[d0 + 1];
        #pragma unroll
        for (int r = 0; r < 16; r++) { acc[r].x = bx; acc[r].y = by; }
        const float* ab = s_a + kg * 16 * 128;
        #pragma unroll 2
        for (int j = 0; j < 128; j++) {
            const float2 w = *(const float2*)(A2 + j * 128 + d0);
            #pragma unroll
            for (int r = 0; r < 16; r++) {
                const float av = ab[r * 128 + j];
                acc[r].x = fmaf(av, w.x, acc[r].x);
                acc[r].y = fmaf(av, w.y, acc[r].y);
            }
        }
        #pragma unroll
        for (int r = 0; r < 16; r++) {
            float2 o; o.x = fmaxf(acc[r].x, 0.f); o.y = fmaxf(acc[r].y, 0.f);
            *(float2*)(s_a2 + (kg * 16 + r) * 128 + d0) = o;
        }
    }
    __syncthreads();

    // ---- Step 5: logits[k] = ab3 + a2[k] . A3 (warp-parallel) ----
    {
        const int wid = t >> 5, lane = t & 31;
        for (int kk = 0; kk < 8; kk++) {
            const int k = wid * 8 + kk;
            float acc = 0.f;
            #pragma unroll
            for (int ii = 0; ii < 4; ii++) {
                const int idx = ii * 32 + lane;
                acc = fmaf(s_a2[k * 128 + idx], s_A3[idx], acc);
            }
            #pragma unroll
            for (int off = 16; off; off >>= 1)
                acc += __shfl_down_sync(0xffffffffu, acc, off);
            if (lane == 0) s_lg[k] = acc + ab3[0];
        }
    }
    __syncthreads();

    // ---- Step 6: softmax over 64 logits (warp 0) ----
    if (t < 32) {
        float l0 = s_lg[t], l1 = s_lg[t + 32];
        float m = fmaxf(l0, l1);
        #pragma unroll
        for (int off = 16; off; off >>= 1)
            m = fmaxf(m, __shfl_xor_sync(0xffffffffu, m, off));
        float e0 = expf(l0 - m), e1 = expf(l1 - m);
        float s = e0 + e1;
        #pragma unroll
        for (int off = 16; off; off >>= 1)
            s += __shfl_xor_sync(0xffffffffu, s, off);
        const float inv = 1.f / s;
        s_lg[t] = e0 * inv;
        s_lg[t + 32] = e1 * inv;
    }
    __syncthreads();

    // ---- Step 7: out[n][d] = sum_k w[k] * h[k][d] ----
    if (t < 128) {
        float acc = 0.f;
        #pragma unroll 4
        for (int k = 0; k < 64; k++)
            acc = fmaf(s_lg[k], s_h[k * 128 + t], acc);
        out[n * 128 + t] = acc;
    }
}

// -------------------------------------------------------------------------
extern "C" void kernel_launch(void* const* d_in, const int* in_sizes, int n_in,
                              void* d_out, int out_size)
{
    const int*   nodes = (const int*)d_in[0];
    const int*   prel  = (const int*)d_in[1];
    const int*   pnbr  = (const int*)d_in[2];
    const int*   attrs = (const int*)d_in[3];
    const float* u2e   = (const float*)d_in[4];
    const float* r2e   = (const float*)d_in[5];
    const float* ua2e  = (const float*)d_in[6];
    const float* W1    = (const float*)d_in[7];
    const float* b1    = (const float*)d_in[8];
    const float* W2    = (const float*)d_in[9];
    const float* b2    = (const float*)d_in[10];
    const float* A1    = (const float*)d_in[11];
    const float* ab1   = (const float*)d_in[12];
    const float* A2    = (const float*)d_in[13];
    const float* ab2   = (const float*)d_in[14];
    const float* A3    = (const float*)d_in[15];
    const float* ab3   = (const float*)d_in[16];
    float* out = (float*)d_out;

    // Precompute folded layer-1 tables (exact linear decomposition of x@W1)
    table_kernel<<<(NU_ + 15) / 16, 256>>>(u2e,  W1 + 256 * 256, NU_, 0);
    table_kernel<<<(NA_ + 15) / 16, 256>>>(ua2e, W1 + 384 * 256, NA_, 1);
    table_kernel<<<2, 256>>>(r2e, W1,             NR_, 2);
    table_kernel<<<2, 256>>>(r2e, W1 + 128 * 256, NR_, 3);
    se_kernel<<<NN, 128>>>(nodes, u2e, A1, ab1);

    cudaFuncSetAttribute(agg_kernel,
                         cudaFuncAttributeMaxDynamicSharedMemorySize, 102400);
    agg_kernel<<<NN, 256, 102400>>>(prel, pnbr, attrs, b1, W2, b2,
                                    A1, A2, A3, ab2, ab3, out);
}